// round 1
// baseline (speedup 1.0000x reference)
#include <cuda_runtime.h>
#include <math.h>
#include <stdint.h>

// Problem dims (fixed by the dataset)
#define T_TOK 8192
#define H_DIM 1024
#define I_DIM 4096
#define S_DIM 128
#define TOPK  16

// ---------------------------------------------------------------------------
// Scratch (static device arrays — no allocation allowed in kernel_launch)
// ---------------------------------------------------------------------------
__device__ float g_h1[(size_t)T_TOK * I_DIM];   // 128 MB: gate proj -> h
__device__ float g_h2[(size_t)T_TOK * I_DIM];   // 128 MB: up proj
__device__ float g_gx[(size_t)T_TOK * S_DIM];   // router gate x logits
__device__ float g_gy[(size_t)T_TOK * S_DIM];   // router gate y logits
__device__ float g_bn[4 * S_DIM];               // [mu_x, inv_x, mu_y, inv_y]
__device__ int   g_ti[(size_t)T_TOK * TOPK];    // selected expert ids
__device__ float g_tw[(size_t)T_TOK * TOPK];    // routing weights (exp of score)

// ---------------------------------------------------------------------------
// Tiled fp32 GEMM:  C[M,N] = A[M,K] @ B[N,K]^T   (both row-major, K-contig)
// 128x128 tile, BK=16, 256 threads, 8x8 micro-tile per thread.
// Assumes M%128==0, N%128==0, K%16==0 (true for all calls here).
// ---------------------------------------------------------------------------
#define BM 128
#define BN 128
#define BK 16
#define SLD (BM + 4)  // padded smem stride to break store bank conflicts

template <bool ACC>
__global__ void __launch_bounds__(256, 2)
gemm_nt(const float* __restrict__ A, const float* __restrict__ B,
        float* __restrict__ C, int M, int N, int K)
{
    __shared__ __align__(16) float As[BK][SLD];
    __shared__ __align__(16) float Bs[BK][SLD];

    const int bm  = blockIdx.y * BM;
    const int bn  = blockIdx.x * BN;
    const int tid = threadIdx.x;
    const int tx  = tid & 15;   // n sub-tile
    const int ty  = tid >> 4;   // m sub-tile

    float acc[8][8];
#pragma unroll
    for (int i = 0; i < 8; i++)
#pragma unroll
        for (int j = 0; j < 8; j++) acc[i][j] = 0.f;

    for (int k0 = 0; k0 < K; k0 += BK) {
#pragma unroll
        for (int p = 0; p < 2; p++) {
            int v   = tid + 256 * p;
            int row = v >> 2;          // 0..127
            int c4  = (v & 3) * 4;     // 0,4,8,12
            float4 a = *(const float4*)(A + (size_t)(bm + row) * K + k0 + c4);
            As[c4 + 0][row] = a.x; As[c4 + 1][row] = a.y;
            As[c4 + 2][row] = a.z; As[c4 + 3][row] = a.w;
            float4 b = *(const float4*)(B + (size_t)(bn + row) * K + k0 + c4);
            Bs[c4 + 0][row] = b.x; Bs[c4 + 1][row] = b.y;
            Bs[c4 + 2][row] = b.z; Bs[c4 + 3][row] = b.w;
        }
        __syncthreads();
#pragma unroll
        for (int kk = 0; kk < BK; kk++) {
            float4 a0 = *(const float4*)&As[kk][ty * 8];
            float4 a1 = *(const float4*)&As[kk][ty * 8 + 4];
            float4 b0 = *(const float4*)&Bs[kk][tx * 8];
            float4 b1 = *(const float4*)&Bs[kk][tx * 8 + 4];
            float ra[8] = {a0.x, a0.y, a0.z, a0.w, a1.x, a1.y, a1.z, a1.w};
            float rb[8] = {b0.x, b0.y, b0.z, b0.w, b1.x, b1.y, b1.z, b1.w};
#pragma unroll
            for (int i = 0; i < 8; i++)
#pragma unroll
                for (int j = 0; j < 8; j++)
                    acc[i][j] = fmaf(ra[i], rb[j], acc[i][j]);
        }
        __syncthreads();
    }

#pragma unroll
    for (int i = 0; i < 8; i++) {
        float* crow = C + (size_t)(bm + ty * 8 + i) * N + bn + tx * 8;
#pragma unroll
        for (int q = 0; q < 2; q++) {
            float4 v = make_float4(acc[i][q * 4 + 0], acc[i][q * 4 + 1],
                                   acc[i][q * 4 + 2], acc[i][q * 4 + 3]);
            if (ACC) {
                float4 c = *(float4*)(crow + q * 4);
                v.x += c.x; v.y += c.y; v.z += c.z; v.w += c.w;
            }
            *(float4*)(crow + q * 4) = v;
        }
    }
}

// ---------------------------------------------------------------------------
// BatchNorm stats: per-feature mean + inv_std over T tokens (biased var).
// blockIdx.x in [0, 2*S): first S -> gate x, next S -> gate y.
// ---------------------------------------------------------------------------
__global__ void bn_stats_kernel(const float* __restrict__ gx,
                                const float* __restrict__ gy,
                                float* __restrict__ bn)
{
    int fb = blockIdx.x;
    const float* src = (fb < S_DIM) ? gx : gy;
    int f    = fb & (S_DIM - 1);
    int base = (fb < S_DIM) ? 0 : 2;

    float s = 0.f, s2 = 0.f;
    for (int r = threadIdx.x; r < T_TOK; r += 256) {
        float v = src[(size_t)r * S_DIM + f];
        s += v; s2 += v * v;
    }
    __shared__ float sh1[256], sh2[256];
    sh1[threadIdx.x] = s; sh2[threadIdx.x] = s2;
    __syncthreads();
    for (int st = 128; st > 0; st >>= 1) {
        if (threadIdx.x < st) {
            sh1[threadIdx.x] += sh1[threadIdx.x + st];
            sh2[threadIdx.x] += sh2[threadIdx.x + st];
        }
        __syncthreads();
    }
    if (threadIdx.x == 0) {
        float mean = sh1[0] / (float)T_TOK;
        float var  = sh2[0] / (float)T_TOK - mean * mean;
        bn[base * S_DIM + f]       = mean;
        bn[(base + 1) * S_DIM + f] = rsqrtf(var + 1e-5f);
    }
}

// ---------------------------------------------------------------------------
// Router: batchnorm-normalize -> log_softmax (x,y) -> top-16 of each ->
// top-16 of the 256 candidate sums. Candidate restriction is exact:
// top-k of a_i + b_j always lies in (top-k of a) x (top-k of b).
// One block (128 threads) per token.
// ---------------------------------------------------------------------------
#define NEG_BIG (-1e30f)

__global__ void __launch_bounds__(128)
router_kernel(const float* __restrict__ gx, const float* __restrict__ gy,
              const float* __restrict__ bn,
              int* __restrict__ ti, float* __restrict__ tw)
{
    const int t = blockIdx.x;
    const int f = threadIdx.x;

    __shared__ float lx[S_DIM], ly[S_DIM];
    __shared__ float rv[S_DIM];
    __shared__ int   ri[S_DIM];
    __shared__ float red[S_DIM];
    __shared__ float tvx[TOPK], tvy[TOPK];
    __shared__ int   tix[TOPK], tiy[TOPK];
    __shared__ float cand[2 * S_DIM];

    float vx = (gx[(size_t)t * S_DIM + f] - bn[f]) * bn[S_DIM + f];
    float vy = (gy[(size_t)t * S_DIM + f] - bn[2 * S_DIM + f]) * bn[3 * S_DIM + f];

    // log_softmax x
    red[f] = vx; __syncthreads();
    for (int s = 64; s > 0; s >>= 1) {
        if (f < s) red[f] = fmaxf(red[f], red[f + s]);
        __syncthreads();
    }
    float mx = red[0]; __syncthreads();
    red[f] = expf(vx - mx); __syncthreads();
    for (int s = 64; s > 0; s >>= 1) {
        if (f < s) red[f] += red[f + s];
        __syncthreads();
    }
    float lsx = mx + logf(red[0]); __syncthreads();
    lx[f] = vx - lsx;

    // log_softmax y
    red[f] = vy; __syncthreads();
    for (int s = 64; s > 0; s >>= 1) {
        if (f < s) red[f] = fmaxf(red[f], red[f + s]);
        __syncthreads();
    }
    float my = red[0]; __syncthreads();
    red[f] = expf(vy - my); __syncthreads();
    for (int s = 64; s > 0; s >>= 1) {
        if (f < s) red[f] += red[f + s];
        __syncthreads();
    }
    float lsy = my + logf(red[0]); __syncthreads();
    ly[f] = vy - lsy;
    __syncthreads();

    // top-16 of lx (iterative argmax; destroys lx)
    for (int r = 0; r < TOPK; r++) {
        rv[f] = lx[f]; ri[f] = f; __syncthreads();
        for (int s = 64; s > 0; s >>= 1) {
            if (f < s && rv[f + s] > rv[f]) { rv[f] = rv[f + s]; ri[f] = ri[f + s]; }
            __syncthreads();
        }
        if (f == 0) { tvx[r] = rv[0]; tix[r] = ri[0]; lx[ri[0]] = NEG_BIG; }
        __syncthreads();
    }
    // top-16 of ly
    for (int r = 0; r < TOPK; r++) {
        rv[f] = ly[f]; ri[f] = f; __syncthreads();
        for (int s = 64; s > 0; s >>= 1) {
            if (f < s && rv[f + s] > rv[f]) { rv[f] = rv[f + s]; ri[f] = ri[f + s]; }
            __syncthreads();
        }
        if (f == 0) { tvy[r] = rv[0]; tiy[r] = ri[0]; ly[ri[0]] = NEG_BIG; }
        __syncthreads();
    }

    // 256 candidates: c = a*16 + b  ->  tvx[a] + tvy[b]
    cand[f]       = tvx[f >> 4]         + tvy[f & 15];
    cand[f + 128] = tvx[(f + 128) >> 4] + tvy[f & 15];
    __syncthreads();

    for (int r = 0; r < TOPK; r++) {
        float v0 = cand[f], v1 = cand[f + 128];
        if (v1 > v0) { rv[f] = v1; ri[f] = f + 128; }
        else         { rv[f] = v0; ri[f] = f; }
        __syncthreads();
        for (int s = 64; s > 0; s >>= 1) {
            if (f < s && rv[f + s] > rv[f]) { rv[f] = rv[f + s]; ri[f] = ri[f + s]; }
            __syncthreads();
        }
        if (f == 0) {
            int c  = ri[0];
            int ai = c >> 4, bi = c & 15;
            ti[t * TOPK + r] = tix[ai] * S_DIM + tiy[bi];
            tw[t * TOPK + r] = expf(rv[0]);
            cand[c] = NEG_BIG;
        }
        __syncthreads();
    }
}

// ---------------------------------------------------------------------------
// Expert branch: out[t] = sum_k (w_k * dot(up_embed[e_k], x_t)) * down_embed[e_k]
// One block (256 threads) per token; x row cached in smem as float4.
// Writes the full output row (experts_states); MLP GEMM then accumulates.
// ---------------------------------------------------------------------------
__global__ void __launch_bounds__(256)
expert_kernel(const float* __restrict__ x,
              const float* __restrict__ up_embed,
              const float* __restrict__ down_embed,
              const int* __restrict__ ti, const float* __restrict__ tw,
              float* __restrict__ out)
{
    const int t   = blockIdx.x;
    const int tid = threadIdx.x;

    __shared__ float4 xs[H_DIM / 4];
    __shared__ float  red[256];
    __shared__ float  sc;

    xs[tid] = ((const float4*)(x + (size_t)t * H_DIM))[tid];
    __syncthreads();

    float4 acc = make_float4(0.f, 0.f, 0.f, 0.f);
    const float4 xv = xs[tid];

#pragma unroll 1
    for (int k = 0; k < TOPK; k++) {
        int e = ti[t * TOPK + k];
        float4 u = ((const float4*)(up_embed + (size_t)e * H_DIM))[tid];
        float p = u.x * xv.x + u.y * xv.y + u.z * xv.z + u.w * xv.w;

        red[tid] = p; __syncthreads();
        if (tid < 128) red[tid] += red[tid + 128]; __syncthreads();
        if (tid < 64)  red[tid] += red[tid + 64];  __syncthreads();
        if (tid < 32) {
            float v = red[tid] + red[tid + 32];
#pragma unroll
            for (int off = 16; off > 0; off >>= 1)
                v += __shfl_down_sync(0xffffffffu, v, off);
            if (tid == 0) sc = v;
        }
        __syncthreads();

        float coef = tw[t * TOPK + k] * sc;
        float4 d = ((const float4*)(down_embed + (size_t)e * H_DIM))[tid];
        acc.x += coef * d.x; acc.y += coef * d.y;
        acc.z += coef * d.z; acc.w += coef * d.w;
        __syncthreads();  // guard red reuse next iteration
    }
    ((float4*)(out + (size_t)t * H_DIM))[tid] = acc;
}

// ---------------------------------------------------------------------------
// h = silu(g) * u  (elementwise, in place on g)
// ---------------------------------------------------------------------------
__global__ void silu_mul_kernel(float* __restrict__ g, const float* __restrict__ u,
                                size_t n4)
{
    float4* g4 = (float4*)g;
    const float4* u4 = (const float4*)u;
    for (size_t i = (size_t)blockIdx.x * blockDim.x + threadIdx.x; i < n4;
         i += (size_t)gridDim.x * blockDim.x) {
        float4 a = g4[i];
        float4 b = u4[i];
        a.x = a.x / (1.f + expf(-a.x)) * b.x;
        a.y = a.y / (1.f + expf(-a.y)) * b.y;
        a.z = a.z / (1.f + expf(-a.z)) * b.z;
        a.w = a.w / (1.f + expf(-a.w)) * b.w;
        g4[i] = a;
    }
}

// ---------------------------------------------------------------------------
// Launch sequence (single stream, graph-capturable, allocation-free)
// ---------------------------------------------------------------------------
extern "C" void kernel_launch(void* const* d_in, const int* in_sizes, int n_in,
                              void* d_out, int out_size)
{
    const float* x   = (const float*)d_in[0];
    const float* wg  = (const float*)d_in[1];
    const float* wu  = (const float*)d_in[2];
    const float* wd  = (const float*)d_in[3];
    const float* wrx = (const float*)d_in[4];
    const float* wry = (const float*)d_in[5];
    const float* ue  = (const float*)d_in[6];
    const float* de  = (const float*)d_in[7];
    float* out = (float*)d_out;

    float *h1, *h2, *gx, *gy, *bn, *tw;
    int* ti;
    cudaGetSymbolAddress((void**)&h1, g_h1);
    cudaGetSymbolAddress((void**)&h2, g_h2);
    cudaGetSymbolAddress((void**)&gx, g_gx);
    cudaGetSymbolAddress((void**)&gy, g_gy);
    cudaGetSymbolAddress((void**)&bn, g_bn);
    cudaGetSymbolAddress((void**)&ti, g_ti);
    cudaGetSymbolAddress((void**)&tw, g_tw);

    // Router gate GEMMs: [T,H] @ [S,H]^T
    gemm_nt<false><<<dim3(S_DIM / BN, T_TOK / BM), 256>>>(x, wrx, gx, T_TOK, S_DIM, H_DIM);
    gemm_nt<false><<<dim3(S_DIM / BN, T_TOK / BM), 256>>>(x, wry, gy, T_TOK, S_DIM, H_DIM);

    // BatchNorm stats + routing top-k
    bn_stats_kernel<<<2 * S_DIM, 256>>>(gx, gy, bn);
    router_kernel<<<T_TOK, 128>>>(gx, gy, bn, ti, tw);

    // Expert branch writes out = experts_states
    expert_kernel<<<T_TOK, 256>>>(x, ue, de, ti, tw, out);

    // Dense MLP
    gemm_nt<false><<<dim3(I_DIM / BN, T_TOK / BM), 256>>>(x, wg, h1, T_TOK, I_DIM, H_DIM);
    gemm_nt<false><<<dim3(I_DIM / BN, T_TOK / BM), 256>>>(x, wu, h2, T_TOK, I_DIM, H_DIM);
    silu_mul_kernel<<<4096, 256>>>(h1, h2, (size_t)T_TOK * I_DIM / 4);

    // out += h @ Wd^T
    gemm_nt<true><<<dim3(H_DIM / BN, T_TOK / BM), 256>>>(h1, wd, out, T_TOK, H_DIM, I_DIM);
}